// round 11
// baseline (speedup 1.0000x reference)
#include <cuda_runtime.h>
#include <cuda_bf16.h>
#include <math.h>

#define NN 100000
#define DD 64
#define EE 1000000
#define EPSM 1e-7f
#define NBLKN 782    // ceil(NN/128) node-tile blocks

// ---------------- scratch (static __device__, no allocation) ----------------
__device__ int   g_count[NN];
__device__ int   g_incl[NN];
__device__ int   g_bsum[128];
__device__ int   g_offset[NN + 1];
__device__ int   g_cursor[NN];
__device__ int   g_ssrc[EE];
__device__ float g_aggout[(size_t)NN * DD];      // 25.6 MB (agg + residual)
__device__ float g_part[(size_t)NBLKN * 256];    // per-block BN partials
__device__ float g_bnscale[128], g_bnshift[128];

// ---------------- tf32 mma helpers ----------------
__device__ __forceinline__ unsigned tf32_of(float f) {
    unsigned u; asm("cvt.rna.tf32.f32 %0, %1;" : "=r"(u) : "f"(f)); return u;
}
__device__ __forceinline__ void mma_tf32(float& d0, float& d1, float& d2, float& d3,
                                         unsigned a0, unsigned a1, unsigned a2, unsigned a3,
                                         unsigned b0, unsigned b1) {
    asm("mma.sync.aligned.m16n8k8.row.col.f32.tf32.tf32.f32 "
        "{%0,%1,%2,%3}, {%4,%5,%6,%7}, {%8,%9}, {%0,%1,%2,%3};"
        : "+f"(d0), "+f"(d1), "+f"(d2), "+f"(d3)
        : "r"(a0), "r"(a1), "r"(a2), "r"(a3), "r"(b0), "r"(b1));
}

// ---------------- 0: zero counters ----------------
__global__ void zero_kernel() {
    unsigned i = blockIdx.x * blockDim.x + threadIdx.x;
    if (i < NN) g_count[i] = 0;
}

// ---------------- 1: histogram of dst ----------------
__global__ void hist_kernel(const int* __restrict__ dst) {
    unsigned e = blockIdx.x * blockDim.x + threadIdx.x;
    if (e < EE) atomicAdd(&g_count[__ldg(dst + e)], 1);
}

// ---------------- 2: per-1024-block inclusive scan ----------------
__global__ void scan1_kernel() {
    __shared__ int s[1024];
    int t = threadIdx.x;
    int i = blockIdx.x * 1024 + t;
    int c = (i < NN) ? g_count[i] : 0;
    s[t] = c;
    __syncthreads();
#pragma unroll
    for (int d = 1; d < 1024; d <<= 1) {
        int v = (t >= d) ? s[t - d] : 0;
        __syncthreads();
        s[t] += v;
        __syncthreads();
    }
    if (i < NN) g_incl[i] = s[t];
    if (t == 1023) g_bsum[blockIdx.x] = s[1023];
}

// ---------------- 3: finalize offsets + cursors (block-prefix fused in) ----------------
__global__ void scan3_kernel() {
    __shared__ int sh[256];
    int t = threadIdx.x;
    int g = blockIdx.x >> 2;           // 1024-group of this 256-block
    sh[t] = (t < g) ? g_bsum[t] : 0;   // g <= 97 < 256
    __syncthreads();
#pragma unroll
    for (int d = 128; d > 0; d >>= 1) {
        if (t < d) sh[t] += sh[t + d];
        __syncthreads();
    }
    int pref = sh[0];
    unsigned i = blockIdx.x * 256 + t;
    if (i < NN) {
        int incl = g_incl[i] + pref;
        g_offset[i + 1] = incl;
        g_cursor[i] = incl - g_count[i];
        if (i == 0) g_offset[0] = 0;
    }
}

// ---------------- 4: scatter edges into CSR order ----------------
__global__ void scatter_kernel(const int* __restrict__ src, const int* __restrict__ dst) {
    unsigned e = blockIdx.x * blockDim.x + threadIdx.x;
    if (e >= EE) return;
    int d = __ldg(dst + e);
    int pos = atomicAdd(&g_cursor[d], 1);
    g_ssrc[pos] = __ldg(src + e);
}

// ---------------- 5: gather-aggregate (warp per node) + residual ----------------
__global__ void __launch_bounds__(256) agg_kernel(const float2* __restrict__ x2) {
    int gw = (blockIdx.x * 256 + threadIdx.x) >> 5;   // node id (uniform per warp)
    int lane = threadIdx.x & 31;
    if (gw >= NN) return;
    int beg = g_offset[gw], end = g_offset[gw + 1];
    float d0 = 0.f, d1 = 0.f, s0 = 0.f, s1 = 0.f;
    for (int base = beg; base < end; base += 32) {
        int m = end - base; if (m > 32) m = 32;
        int sl = (lane < m) ? __ldg(g_ssrc + base + lane) : 0;
#pragma unroll 4
        for (int i = 0; i < m; i++) {
            int s = __shfl_sync(0xFFFFFFFFu, sl, i);
            float2 v = __ldg(x2 + (size_t)s * 32 + lane);
            float m0 = fmaxf(v.x, 0.f) + EPSM;
            float m1 = fmaxf(v.y, 0.f) + EPSM;
            float e0 = __expf(m0), e1 = __expf(m1);
            d0 += e0; d1 += e1;
            s0 = fmaf(m0, e0, s0); s1 = fmaf(m1, e1, s1);
        }
    }
    float2 self = __ldg(x2 + (size_t)gw * 32 + lane);
    float2 r;
    r.x = s0 / (d0 + 1e-16f) + self.x;
    r.y = s1 / (d1 + 1e-16f) + self.y;
    reinterpret_cast<float2*>(g_aggout)[(size_t)gw * 32 + lane] = r;
}

// ---------------- 6: BN statistics via tf32 mma (NO h materialization) ----------------
// 128 nodes/block, 256 threads (8 warps). Warp w -> rows 16w..16w+15, all 128 cols.
#define A_PAD 68
#define W1_PAD 136
#define STATSA_SMEM ((128 * A_PAD + 64 * W1_PAD + 2048) * 4)
__global__ void __launch_bounds__(256) statsA_kernel(const float* __restrict__ W1,
                                                     const float* __restrict__ b1) {
    extern __shared__ __align__(16) unsigned sm_u[];
    unsigned* s_a = sm_u;                          // [128][A_PAD]
    unsigned* s_w = sm_u + 128 * A_PAD;            // [64][W1_PAD]
    float*    s_red = (float*)(sm_u + 128 * A_PAD + 64 * W1_PAD);  // [2][8][128]
    int t = threadIdx.x;
    int nb = blockIdx.x * 128;

    for (int i = t; i < 128 * 64; i += 256) {
        int n = i >> 6, k = i & 63;
        float v = (nb + n < NN) ? g_aggout[(size_t)(nb + n) * 64 + k] : 0.f;
        s_a[n * A_PAD + k] = tf32_of(v);
    }
    for (int i = t; i < 64 * 128; i += 256) {
        int k = i >> 7, c = i & 127;
        s_w[k * W1_PAD + c] = tf32_of(__ldg(W1 + i));
    }
    __syncthreads();

    int lane = t & 31, w = t >> 5;
    int gid = lane >> 2, tig = lane & 3;
    int m0 = w * 16;
    float d[16][4];
#pragma unroll
    for (int nt = 0; nt < 16; nt++) {
        float bA = __ldg(b1 + nt * 8 + 2 * tig);
        float bB = __ldg(b1 + nt * 8 + 2 * tig + 1);
        d[nt][0] = bA; d[nt][1] = bB; d[nt][2] = bA; d[nt][3] = bB;
    }

#pragma unroll
    for (int ks = 0; ks < 8; ks++) {
        int k0 = ks * 8;
        unsigned a0 = s_a[(m0 + gid) * A_PAD + k0 + tig];
        unsigned a1 = s_a[(m0 + gid + 8) * A_PAD + k0 + tig];
        unsigned a2 = s_a[(m0 + gid) * A_PAD + k0 + tig + 4];
        unsigned a3 = s_a[(m0 + gid + 8) * A_PAD + k0 + tig + 4];
#pragma unroll
        for (int nt = 0; nt < 16; nt++) {
            unsigned bb0 = s_w[(k0 + tig) * W1_PAD + nt * 8 + gid];
            unsigned bb1 = s_w[(k0 + tig + 4) * W1_PAD + nt * 8 + gid];
            mma_tf32(d[nt][0], d[nt][1], d[nt][2], d[nt][3], a0, a1, a2, a3, bb0, bb1);
        }
    }

    // reduce BN partials per column (no h store)
    int r0 = nb + m0 + gid, r1 = r0 + 8;
    bool ok0 = r0 < NN, ok1 = r1 < NN;
#pragma unroll
    for (int nt = 0; nt < 16; nt++) {
        float e0 = d[nt][0], e1 = d[nt][1], e2 = d[nt][2], e3 = d[nt][3];
        int cA = nt * 8 + 2 * tig;
        float sA = (ok0 ? e0 : 0.f) + (ok1 ? e2 : 0.f);
        float sB = (ok0 ? e1 : 0.f) + (ok1 ? e3 : 0.f);
        float qA = (ok0 ? e0 * e0 : 0.f) + (ok1 ? e2 * e2 : 0.f);
        float qB = (ok0 ? e1 * e1 : 0.f) + (ok1 ? e3 * e3 : 0.f);
#pragma unroll
        for (int off = 4; off < 32; off <<= 1) {
            sA += __shfl_xor_sync(0xFFFFFFFFu, sA, off);
            sB += __shfl_xor_sync(0xFFFFFFFFu, sB, off);
            qA += __shfl_xor_sync(0xFFFFFFFFu, qA, off);
            qB += __shfl_xor_sync(0xFFFFFFFFu, qB, off);
        }
        if (gid == 0) {
            s_red[w * 128 + cA]            = sA;
            s_red[w * 128 + cA + 1]        = sB;
            s_red[1024 + w * 128 + cA]     = qA;
            s_red[1024 + w * 128 + cA + 1] = qB;
        }
    }
    __syncthreads();
    if (t < 128) {
        float a = 0.f, b = 0.f;
#pragma unroll
        for (int ww = 0; ww < 8; ww++) {
            a += s_red[ww * 128 + t];
            b += s_red[1024 + ww * 128 + t];
        }
        g_part[(size_t)blockIdx.x * 256 + t]       = a;
        g_part[(size_t)blockIdx.x * 256 + 128 + t] = b;
    }
}

// ---------------- 7: BN finalize (parallel reduce of partials) ----------------
__global__ void __launch_bounds__(1024) bnfin_kernel(const float* __restrict__ gam,
                                                     const float* __restrict__ bet) {
    __shared__ float s1[1024], s2[1024];
    int t = threadIdx.x;
    int c = t & 127, seg = t >> 7;   // 8 segments
    float s = 0.f, q = 0.f;
    for (int b = seg; b < NBLKN; b += 8) {
        s += g_part[(size_t)b * 256 + c];
        q += g_part[(size_t)b * 256 + 128 + c];
    }
    s1[t] = s; s2[t] = q;
    __syncthreads();
    if (t < 128) {
        float ss = 0.f, qq = 0.f;
#pragma unroll
        for (int j = 0; j < 8; j++) { ss += s1[j * 128 + t]; qq += s2[j * 128 + t]; }
        float mean = ss * (1.f / (float)NN);
        float var = qq * (1.f / (float)NN) - mean * mean;
        float sc = __ldg(gam + t) * rsqrtf(var + 1e-5f);
        g_bnscale[t] = sc;
        g_bnshift[t] = __ldg(bet + t) - mean * sc;
    }
}

// ---------------- 8: FUSED Linear1 -> BN+ReLU -> Linear2 -> LayerNorm -> ReLU ----------------
// 128 nodes/block, 256 threads. h recomputed in-block (never touches DRAM).
#define H_PAD 132
#define W2_PAD 72
#define NODEB_SMEM ((128 * A_PAD + 64 * W1_PAD + 128 * H_PAD + 128 * W2_PAD) * 4)
__global__ void __launch_bounds__(256) nodeB_kernel(const float* __restrict__ W1,
                                                    const float* __restrict__ b1,
                                                    const float* __restrict__ W2,
                                                    const float* __restrict__ b2,
                                                    const float* __restrict__ lng,
                                                    const float* __restrict__ lnb,
                                                    float* __restrict__ out) {
    extern __shared__ __align__(16) unsigned sm_u[];
    unsigned* s_in = sm_u;                                   // [128][A_PAD]
    unsigned* s_w1 = sm_u + 128 * A_PAD;                     // [64][W1_PAD]
    unsigned* s_h  = s_w1 + 64 * W1_PAD;                     // [128][H_PAD]
    unsigned* s_w2 = s_h + 128 * H_PAD;                      // [128][W2_PAD]
    int t = threadIdx.x;
    int nb = blockIdx.x * 128;

    for (int i = t; i < 128 * 64; i += 256) {
        int n = i >> 6, k = i & 63;
        float v = (nb + n < NN) ? g_aggout[(size_t)(nb + n) * 64 + k] : 0.f;
        s_in[n * A_PAD + k] = tf32_of(v);
    }
    for (int i = t; i < 64 * 128; i += 256) {
        int k = i >> 7, c = i & 127;
        s_w1[k * W1_PAD + c] = tf32_of(__ldg(W1 + i));
    }
    for (int i = t; i < 128 * 64; i += 256) {
        int k = i >> 6, c = i & 63;
        s_w2[k * W2_PAD + c] = tf32_of(__ldg(W2 + i));
    }
    __syncthreads();

    int lane = t & 31, w = t >> 5;
    int gid = lane >> 2, tig = lane & 3;
    int m0 = w * 16;

    // ---- MMA1: h = in @ W1 + b1 ----
    float d1[16][4];
#pragma unroll
    for (int nt = 0; nt < 16; nt++) {
        float bA = __ldg(b1 + nt * 8 + 2 * tig);
        float bB = __ldg(b1 + nt * 8 + 2 * tig + 1);
        d1[nt][0] = bA; d1[nt][1] = bB; d1[nt][2] = bA; d1[nt][3] = bB;
    }
#pragma unroll
    for (int ks = 0; ks < 8; ks++) {
        int k0 = ks * 8;
        unsigned a0 = s_in[(m0 + gid) * A_PAD + k0 + tig];
        unsigned a1 = s_in[(m0 + gid + 8) * A_PAD + k0 + tig];
        unsigned a2 = s_in[(m0 + gid) * A_PAD + k0 + tig + 4];
        unsigned a3 = s_in[(m0 + gid + 8) * A_PAD + k0 + tig + 4];
#pragma unroll
        for (int nt = 0; nt < 16; nt++) {
            unsigned bb0 = s_w1[(k0 + tig) * W1_PAD + nt * 8 + gid];
            unsigned bb1 = s_w1[(k0 + tig + 4) * W1_PAD + nt * 8 + gid];
            mma_tf32(d1[nt][0], d1[nt][1], d1[nt][2], d1[nt][3], a0, a1, a2, a3, bb0, bb1);
        }
    }

    // ---- BN + ReLU on fragments -> tf32 into s_h ----
    int rl0 = m0 + gid, rl1 = rl0 + 8;
#pragma unroll
    for (int nt = 0; nt < 16; nt++) {
        int cA = nt * 8 + 2 * tig;
        float scA = g_bnscale[cA], shA = g_bnshift[cA];
        float scB = g_bnscale[cA + 1], shB = g_bnshift[cA + 1];
        s_h[rl0 * H_PAD + cA]     = tf32_of(fmaxf(fmaf(d1[nt][0], scA, shA), 0.f));
        s_h[rl0 * H_PAD + cA + 1] = tf32_of(fmaxf(fmaf(d1[nt][1], scB, shB), 0.f));
        s_h[rl1 * H_PAD + cA]     = tf32_of(fmaxf(fmaf(d1[nt][2], scA, shA), 0.f));
        s_h[rl1 * H_PAD + cA + 1] = tf32_of(fmaxf(fmaf(d1[nt][3], scB, shB), 0.f));
    }
    __syncthreads();

    // ---- MMA2: y = h @ W2 + b2 ----
    float d2[8][4];
#pragma unroll
    for (int nt = 0; nt < 8; nt++) {
        float bA = __ldg(b2 + nt * 8 + 2 * tig);
        float bB = __ldg(b2 + nt * 8 + 2 * tig + 1);
        d2[nt][0] = bA; d2[nt][1] = bB; d2[nt][2] = bA; d2[nt][3] = bB;
    }
#pragma unroll
    for (int ks = 0; ks < 16; ks++) {
        int k0 = ks * 8;
        unsigned a0 = s_h[(m0 + gid) * H_PAD + k0 + tig];
        unsigned a1 = s_h[(m0 + gid + 8) * H_PAD + k0 + tig];
        unsigned a2 = s_h[(m0 + gid) * H_PAD + k0 + tig + 4];
        unsigned a3 = s_h[(m0 + gid + 8) * H_PAD + k0 + tig + 4];
#pragma unroll
        for (int nt = 0; nt < 8; nt++) {
            unsigned bb0 = s_w2[(k0 + tig) * W2_PAD + nt * 8 + gid];
            unsigned bb1 = s_w2[(k0 + tig + 4) * W2_PAD + nt * 8 + gid];
            mma_tf32(d2[nt][0], d2[nt][1], d2[nt][2], d2[nt][3], a0, a1, a2, a3, bb0, bb1);
        }
    }

    // ---- LayerNorm + ReLU on fragments ----
    float rs0 = 0.f, rq0 = 0.f, rs1 = 0.f, rq1 = 0.f;
#pragma unroll
    for (int nt = 0; nt < 8; nt++) {
        rs0 += d2[nt][0] + d2[nt][1];
        rq0 += d2[nt][0] * d2[nt][0] + d2[nt][1] * d2[nt][1];
        rs1 += d2[nt][2] + d2[nt][3];
        rq1 += d2[nt][2] * d2[nt][2] + d2[nt][3] * d2[nt][3];
    }
#pragma unroll
    for (int off = 1; off < 4; off <<= 1) {
        rs0 += __shfl_xor_sync(0xFFFFFFFFu, rs0, off);
        rq0 += __shfl_xor_sync(0xFFFFFFFFu, rq0, off);
        rs1 += __shfl_xor_sync(0xFFFFFFFFu, rs1, off);
        rq1 += __shfl_xor_sync(0xFFFFFFFFu, rq1, off);
    }
    float mean0 = rs0 * (1.f / 64.f);
    float var0  = rq0 * (1.f / 64.f) - mean0 * mean0;
    float inv0  = rsqrtf(var0 + 1e-5f);
    float mean1 = rs1 * (1.f / 64.f);
    float var1  = rq1 * (1.f / 64.f) - mean1 * mean1;
    float inv1  = rsqrtf(var1 + 1e-5f);

    int r0 = nb + m0 + gid, r1 = r0 + 8;
    bool ok0 = r0 < NN, ok1 = r1 < NN;
#pragma unroll
    for (int nt = 0; nt < 8; nt++) {
        int cA = nt * 8 + 2 * tig;
        float gA = __ldg(lng + cA), gB = __ldg(lng + cA + 1);
        float bA = __ldg(lnb + cA), bB = __ldg(lnb + cA + 1);
        if (ok0) {
            float y0 = fmaxf((d2[nt][0] - mean0) * inv0 * gA + bA, 0.f);
            float y1 = fmaxf((d2[nt][1] - mean0) * inv0 * gB + bB, 0.f);
            *reinterpret_cast<float2*>(&out[(size_t)r0 * 64 + cA]) = make_float2(y0, y1);
        }
        if (ok1) {
            float y2 = fmaxf((d2[nt][2] - mean1) * inv1 * gA + bA, 0.f);
            float y3 = fmaxf((d2[nt][3] - mean1) * inv1 * gB + bB, 0.f);
            *reinterpret_cast<float2*>(&out[(size_t)r1 * 64 + cA]) = make_float2(y2, y3);
        }
    }
}

// ---------------- launcher ----------------
extern "C" void kernel_launch(void* const* d_in, const int* in_sizes, int n_in,
                              void* d_out, int out_size) {
    const float* x   = (const float*)d_in[0];
    const int*   ei  = (const int*)d_in[1];
    const float* W1  = (const float*)d_in[2];
    const float* b1  = (const float*)d_in[3];
    const float* bng = (const float*)d_in[4];
    const float* bnb = (const float*)d_in[5];
    const float* W2  = (const float*)d_in[6];
    const float* b2  = (const float*)d_in[7];
    const float* lng = (const float*)d_in[8];
    const float* lnb = (const float*)d_in[9];
    float* out = (float*)d_out;

    const int* src = ei;        // edge_index[0]
    const int* dst = ei + EE;   // edge_index[1]

    cudaFuncSetAttribute(statsA_kernel, cudaFuncAttributeMaxDynamicSharedMemorySize, STATSA_SMEM);
    cudaFuncSetAttribute(nodeB_kernel, cudaFuncAttributeMaxDynamicSharedMemorySize, NODEB_SMEM);

    const int nscan = (NN + 1023) / 1024;   // 98

    zero_kernel<<<(NN + 255) / 256, 256>>>();                                  // 0
    hist_kernel<<<(EE + 255) / 256, 256>>>(dst);                               // 1
    scan1_kernel<<<nscan, 1024>>>();                                           // 2
    scan3_kernel<<<(NN + 255) / 256, 256>>>();                                 // 3
    scatter_kernel<<<(EE + 255) / 256, 256>>>(src, dst);                       // 4
    agg_kernel<<<(NN * 32 + 255) / 256, 256>>>((const float2*)x);              // 5
    statsA_kernel<<<NBLKN, 256, STATSA_SMEM>>>(W1, b1);                        // 6
    bnfin_kernel<<<1, 1024>>>(bng, bnb);                                       // 7
    nodeB_kernel<<<NBLKN, 256, NODEB_SMEM>>>(W1, b1, W2, b2, lng, lnb, out);   // 8
}

// round 12
// speedup vs baseline: 1.1735x; 1.1735x over previous
#include <cuda_runtime.h>
#include <cuda_bf16.h>
#include <cuda_fp16.h>
#include <math.h>

#define NN 100000
#define DD 64
#define EE 1000000
#define EPSM 1e-7f
#define NBLKN 782    // ceil(NN/128) node-tile blocks

// ---------------- scratch (static __device__, no allocation) ----------------
__device__ int    g_count[NN];          // zeroed at load; re-zeroed by scan3 each run
__device__ int    g_incl[NN];
__device__ int    g_bsum[128];
__device__ int    g_offset[NN + 1];
__device__ int    g_cursor[NN];
__device__ int    g_ssrc[EE];
__device__ float  g_aggout[(size_t)NN * DD];     // 25.6 MB (agg + residual)
__device__ __half g_h16[(size_t)NN * 128];       // 25.6 MB hidden (pre-BN, fp16)
__device__ float  g_part[(size_t)NBLKN * 256];   // per-block BN partials
__device__ float  g_bnscale[128], g_bnshift[128];

// ---------------- tf32 mma helpers ----------------
__device__ __forceinline__ unsigned tf32_of(float f) {
    unsigned u; asm("cvt.rna.tf32.f32 %0, %1;" : "=r"(u) : "f"(f)); return u;
}
__device__ __forceinline__ void mma_tf32(float& d0, float& d1, float& d2, float& d3,
                                         unsigned a0, unsigned a1, unsigned a2, unsigned a3,
                                         unsigned b0, unsigned b1) {
    asm("mma.sync.aligned.m16n8k8.row.col.f32.tf32.tf32.f32 "
        "{%0,%1,%2,%3}, {%4,%5,%6,%7}, {%8,%9}, {%0,%1,%2,%3};"
        : "+f"(d0), "+f"(d1), "+f"(d2), "+f"(d3)
        : "r"(a0), "r"(a1), "r"(a2), "r"(a3), "r"(b0), "r"(b1));
}

// ---------------- 0: histogram of dst (g_count pre-zeroed) ----------------
__global__ void hist_kernel(const int* __restrict__ dst) {
    unsigned e = blockIdx.x * blockDim.x + threadIdx.x;
    if (e < EE) atomicAdd(&g_count[__ldg(dst + e)], 1);
}

// ---------------- 1: per-1024-block inclusive scan ----------------
__global__ void scan1_kernel() {
    __shared__ int s[1024];
    int t = threadIdx.x;
    int i = blockIdx.x * 1024 + t;
    int c = (i < NN) ? g_count[i] : 0;
    s[t] = c;
    __syncthreads();
#pragma unroll
    for (int d = 1; d < 1024; d <<= 1) {
        int v = (t >= d) ? s[t - d] : 0;
        __syncthreads();
        s[t] += v;
        __syncthreads();
    }
    if (i < NN) g_incl[i] = s[t];
    if (t == 1023) g_bsum[blockIdx.x] = s[1023];
}

// ---------------- 2: finalize offsets + cursors + RE-ZERO counts ----------------
__global__ void scan3_kernel() {
    __shared__ int sh[256];
    int t = threadIdx.x;
    int g = blockIdx.x >> 2;           // 1024-group of this 256-block
    sh[t] = (t < g) ? g_bsum[t] : 0;   // g <= 97 < 256
    __syncthreads();
#pragma unroll
    for (int d = 128; d > 0; d >>= 1) {
        if (t < d) sh[t] += sh[t + d];
        __syncthreads();
    }
    int pref = sh[0];
    unsigned i = blockIdx.x * 256 + t;
    if (i < NN) {
        int cnt = g_count[i];
        int incl = g_incl[i] + pref;
        g_offset[i + 1] = incl;
        g_cursor[i] = incl - cnt;
        g_count[i] = 0;                // ready for next graph replay
        if (i == 0) g_offset[0] = 0;
    }
}

// ---------------- 3: scatter edges into CSR order ----------------
__global__ void scatter_kernel(const int* __restrict__ src, const int* __restrict__ dst) {
    unsigned e = blockIdx.x * blockDim.x + threadIdx.x;
    if (e >= EE) return;
    int d = __ldg(dst + e);
    int pos = atomicAdd(&g_cursor[d], 1);
    g_ssrc[pos] = __ldg(src + e);
}

// ---------------- 4: gather-aggregate (warp per node) + residual ----------------
__global__ void __launch_bounds__(256) agg_kernel(const float2* __restrict__ x2) {
    int gw = (blockIdx.x * 256 + threadIdx.x) >> 5;   // node id (uniform per warp)
    int lane = threadIdx.x & 31;
    if (gw >= NN) return;
    int beg = g_offset[gw], end = g_offset[gw + 1];
    float d0 = 0.f, d1 = 0.f, s0 = 0.f, s1 = 0.f;
    for (int base = beg; base < end; base += 32) {
        int m = end - base; if (m > 32) m = 32;
        int sl = (lane < m) ? __ldg(g_ssrc + base + lane) : 0;
#pragma unroll 4
        for (int i = 0; i < m; i++) {
            int s = __shfl_sync(0xFFFFFFFFu, sl, i);
            float2 v = __ldg(x2 + (size_t)s * 32 + lane);
            float m0 = fmaxf(v.x, 0.f) + EPSM;
            float m1 = fmaxf(v.y, 0.f) + EPSM;
            float e0 = __expf(m0), e1 = __expf(m1);
            d0 += e0; d1 += e1;
            s0 = fmaf(m0, e0, s0); s1 = fmaf(m1, e1, s1);
        }
    }
    float2 self = __ldg(x2 + (size_t)gw * 32 + lane);
    float2 r;
    r.x = s0 / (d0 + 1e-16f) + self.x;
    r.y = s1 / (d1 + 1e-16f) + self.y;
    reinterpret_cast<float2*>(g_aggout)[(size_t)gw * 32 + lane] = r;
}

// ---------------- 5: Linear1 via tf32 mma + h store (fp16) + BN partials ----------------
// 128 nodes/block, 256 threads (8 warps). Warp w -> rows 16w..16w+15, all 128 cols.
#define A_PAD 68
#define W1_PAD 136
#define NODEA_SMEM ((128 * A_PAD + 64 * W1_PAD + 2048) * 4)
__global__ void __launch_bounds__(256) nodeA_kernel(const float* __restrict__ W1,
                                                    const float* __restrict__ b1) {
    extern __shared__ __align__(16) unsigned sm_u[];
    unsigned* s_a = sm_u;                          // [128][A_PAD]
    unsigned* s_w = sm_u + 128 * A_PAD;            // [64][W1_PAD]
    float*    s_red = (float*)(sm_u + 128 * A_PAD + 64 * W1_PAD);  // [2][8][128]
    int t = threadIdx.x;
    int nb = blockIdx.x * 128;

    for (int i = t; i < 128 * 64; i += 256) {
        int n = i >> 6, k = i & 63;
        float v = (nb + n < NN) ? g_aggout[(size_t)(nb + n) * 64 + k] : 0.f;
        s_a[n * A_PAD + k] = tf32_of(v);
    }
    for (int i = t; i < 64 * 128; i += 256) {
        int k = i >> 7, c = i & 127;
        s_w[k * W1_PAD + c] = tf32_of(__ldg(W1 + i));
    }
    __syncthreads();

    int lane = t & 31, w = t >> 5;
    int gid = lane >> 2, tig = lane & 3;
    int m0 = w * 16;
    float d[16][4];
#pragma unroll
    for (int nt = 0; nt < 16; nt++) {
        float bA = __ldg(b1 + nt * 8 + 2 * tig);
        float bB = __ldg(b1 + nt * 8 + 2 * tig + 1);
        d[nt][0] = bA; d[nt][1] = bB; d[nt][2] = bA; d[nt][3] = bB;
    }

#pragma unroll
    for (int ks = 0; ks < 8; ks++) {
        int k0 = ks * 8;
        unsigned a0 = s_a[(m0 + gid) * A_PAD + k0 + tig];
        unsigned a1 = s_a[(m0 + gid + 8) * A_PAD + k0 + tig];
        unsigned a2 = s_a[(m0 + gid) * A_PAD + k0 + tig + 4];
        unsigned a3 = s_a[(m0 + gid + 8) * A_PAD + k0 + tig + 4];
#pragma unroll
        for (int nt = 0; nt < 16; nt++) {
            unsigned bb0 = s_w[(k0 + tig) * W1_PAD + nt * 8 + gid];
            unsigned bb1 = s_w[(k0 + tig + 4) * W1_PAD + nt * 8 + gid];
            mma_tf32(d[nt][0], d[nt][1], d[nt][2], d[nt][3], a0, a1, a2, a3, bb0, bb1);
        }
    }

    // epilogue: store h (fp16), warp-reduce BN partials per column
    int r0 = nb + m0 + gid, r1 = r0 + 8;
    bool ok0 = r0 < NN, ok1 = r1 < NN;
#pragma unroll
    for (int nt = 0; nt < 16; nt++) {
        float e0 = d[nt][0], e1 = d[nt][1], e2 = d[nt][2], e3 = d[nt][3];
        int cA = nt * 8 + 2 * tig;
        if (ok0) *reinterpret_cast<__half2*>(&g_h16[(size_t)r0 * 128 + cA]) = __floats2half2_rn(e0, e1);
        if (ok1) *reinterpret_cast<__half2*>(&g_h16[(size_t)r1 * 128 + cA]) = __floats2half2_rn(e2, e3);
        float sA = (ok0 ? e0 : 0.f) + (ok1 ? e2 : 0.f);
        float sB = (ok0 ? e1 : 0.f) + (ok1 ? e3 : 0.f);
        float qA = (ok0 ? e0 * e0 : 0.f) + (ok1 ? e2 * e2 : 0.f);
        float qB = (ok0 ? e1 * e1 : 0.f) + (ok1 ? e3 * e3 : 0.f);
#pragma unroll
        for (int off = 4; off < 32; off <<= 1) {
            sA += __shfl_xor_sync(0xFFFFFFFFu, sA, off);
            sB += __shfl_xor_sync(0xFFFFFFFFu, sB, off);
            qA += __shfl_xor_sync(0xFFFFFFFFu, qA, off);
            qB += __shfl_xor_sync(0xFFFFFFFFu, qB, off);
        }
        if (gid == 0) {
            s_red[w * 128 + cA]            = sA;
            s_red[w * 128 + cA + 1]        = sB;
            s_red[1024 + w * 128 + cA]     = qA;
            s_red[1024 + w * 128 + cA + 1] = qB;
        }
    }
    __syncthreads();
    if (t < 128) {
        float a = 0.f, b = 0.f;
#pragma unroll
        for (int ww = 0; ww < 8; ww++) {
            a += s_red[ww * 128 + t];
            b += s_red[1024 + ww * 128 + t];
        }
        g_part[(size_t)blockIdx.x * 256 + t]       = a;
        g_part[(size_t)blockIdx.x * 256 + 128 + t] = b;
    }
}

// ---------------- 6: BN finalize (parallel reduce of partials) ----------------
__global__ void __launch_bounds__(1024) bnfin_kernel(const float* __restrict__ gam,
                                                     const float* __restrict__ bet) {
    __shared__ float s1[1024], s2[1024];
    int t = threadIdx.x;
    int c = t & 127, seg = t >> 7;   // 8 segments
    float s = 0.f, q = 0.f;
    for (int b = seg; b < NBLKN; b += 8) {
        s += g_part[(size_t)b * 256 + c];
        q += g_part[(size_t)b * 256 + 128 + c];
    }
    s1[t] = s; s2[t] = q;
    __syncthreads();
    if (t < 128) {
        float ss = 0.f, qq = 0.f;
#pragma unroll
        for (int j = 0; j < 8; j++) { ss += s1[j * 128 + t]; qq += s2[j * 128 + t]; }
        float mean = ss * (1.f / (float)NN);
        float var = qq * (1.f / (float)NN) - mean * mean;
        float sc = __ldg(gam + t) * rsqrtf(var + 1e-5f);
        g_bnscale[t] = sc;
        g_bnshift[t] = __ldg(bet + t) - mean * sc;
    }
}

// ---------------- 7: BN+ReLU + Linear2 (tf32 mma) + LayerNorm + ReLU ----------------
// 128 nodes/block, 256 threads. Warp w -> rows 16w..16w+15, all 64 cols.
#define B_APAD 132
#define W2_PAD 72
#define NODEB_SMEM ((128 * B_APAD + 128 * W2_PAD) * 4)
__global__ void __launch_bounds__(256) nodeB_kernel(const float* __restrict__ W2,
                                                    const float* __restrict__ b2,
                                                    const float* __restrict__ lng,
                                                    const float* __restrict__ lnb,
                                                    float* __restrict__ out) {
    extern __shared__ __align__(16) unsigned sm_u[];
    unsigned* s_a = sm_u;                  // [128][B_APAD]
    unsigned* s_w = sm_u + 128 * B_APAD;   // [128][W2_PAD]
    int t = threadIdx.x;
    int nb = blockIdx.x * 128;

    // stage h (fp16 -> BN+ReLU -> tf32)
    const __half2* hh = reinterpret_cast<const __half2*>(g_h16);
    for (int p = t; p < 128 * 64; p += 256) {
        int n = p >> 6, j = p & 63;
        int k = 2 * j;
        float f0 = 0.f, f1 = 0.f;
        if (nb + n < NN) {
            __half2 v2 = hh[(size_t)(nb + n) * 64 + j];
            f0 = __low2float(v2);
            f1 = __high2float(v2);
            f0 = fmaxf(fmaf(f0, g_bnscale[k],     g_bnshift[k]),     0.f);
            f1 = fmaxf(fmaf(f1, g_bnscale[k + 1], g_bnshift[k + 1]), 0.f);
        }
        s_a[n * B_APAD + k]     = tf32_of(f0);
        s_a[n * B_APAD + k + 1] = tf32_of(f1);
    }
    for (int i = t; i < 128 * 64; i += 256) {
        int k = i >> 6, c = i & 63;
        s_w[k * W2_PAD + c] = tf32_of(__ldg(W2 + i));
    }
    __syncthreads();

    int lane = t & 31, w = t >> 5;
    int gid = lane >> 2, tig = lane & 3;
    int m0 = w * 16;
    float d[8][4];
#pragma unroll
    for (int nt = 0; nt < 8; nt++) {
        float bA = __ldg(b2 + nt * 8 + 2 * tig);
        float bB = __ldg(b2 + nt * 8 + 2 * tig + 1);
        d[nt][0] = bA; d[nt][1] = bB; d[nt][2] = bA; d[nt][3] = bB;
    }

#pragma unroll
    for (int ks = 0; ks < 16; ks++) {
        int k0 = ks * 8;
        unsigned a0 = s_a[(m0 + gid) * B_APAD + k0 + tig];
        unsigned a1 = s_a[(m0 + gid + 8) * B_APAD + k0 + tig];
        unsigned a2 = s_a[(m0 + gid) * B_APAD + k0 + tig + 4];
        unsigned a3 = s_a[(m0 + gid + 8) * B_APAD + k0 + tig + 4];
#pragma unroll
        for (int nt = 0; nt < 8; nt++) {
            unsigned bb0 = s_w[(k0 + tig) * W2_PAD + nt * 8 + gid];
            unsigned bb1 = s_w[(k0 + tig + 4) * W2_PAD + nt * 8 + gid];
            mma_tf32(d[nt][0], d[nt][1], d[nt][2], d[nt][3], a0, a1, a2, a3, bb0, bb1);
        }
    }

    // LayerNorm per row directly on fragments
    float rs0 = 0.f, rq0 = 0.f, rs1 = 0.f, rq1 = 0.f;
#pragma unroll
    for (int nt = 0; nt < 8; nt++) {
        rs0 += d[nt][0] + d[nt][1];
        rq0 += d[nt][0] * d[nt][0] + d[nt][1] * d[nt][1];
        rs1 += d[nt][2] + d[nt][3];
        rq1 += d[nt][2] * d[nt][2] + d[nt][3] * d[nt][3];
    }
#pragma unroll
    for (int off = 1; off < 4; off <<= 1) {
        rs0 += __shfl_xor_sync(0xFFFFFFFFu, rs0, off);
        rq0 += __shfl_xor_sync(0xFFFFFFFFu, rq0, off);
        rs1 += __shfl_xor_sync(0xFFFFFFFFu, rs1, off);
        rq1 += __shfl_xor_sync(0xFFFFFFFFu, rq1, off);
    }
    float mean0 = rs0 * (1.f / 64.f);
    float var0  = rq0 * (1.f / 64.f) - mean0 * mean0;
    float inv0  = rsqrtf(var0 + 1e-5f);
    float mean1 = rs1 * (1.f / 64.f);
    float var1  = rq1 * (1.f / 64.f) - mean1 * mean1;
    float inv1  = rsqrtf(var1 + 1e-5f);

    int r0 = nb + m0 + gid, r1 = r0 + 8;
    bool ok0 = r0 < NN, ok1 = r1 < NN;
#pragma unroll
    for (int nt = 0; nt < 8; nt++) {
        int cA = nt * 8 + 2 * tig;
        float gA = __ldg(lng + cA), gB = __ldg(lng + cA + 1);
        float bA = __ldg(lnb + cA), bB = __ldg(lnb + cA + 1);
        if (ok0) {
            float y0 = fmaxf((d[nt][0] - mean0) * inv0 * gA + bA, 0.f);
            float y1 = fmaxf((d[nt][1] - mean0) * inv0 * gB + bB, 0.f);
            *reinterpret_cast<float2*>(&out[(size_t)r0 * 64 + cA]) = make_float2(y0, y1);
        }
        if (ok1) {
            float y2 = fmaxf((d[nt][2] - mean1) * inv1 * gA + bA, 0.f);
            float y3 = fmaxf((d[nt][3] - mean1) * inv1 * gB + bB, 0.f);
            *reinterpret_cast<float2*>(&out[(size_t)r1 * 64 + cA]) = make_float2(y2, y3);
        }
    }
}

// ---------------- launcher ----------------
extern "C" void kernel_launch(void* const* d_in, const int* in_sizes, int n_in,
                              void* d_out, int out_size) {
    const float* x   = (const float*)d_in[0];
    const int*   ei  = (const int*)d_in[1];
    const float* W1  = (const float*)d_in[2];
    const float* b1  = (const float*)d_in[3];
    const float* bng = (const float*)d_in[4];
    const float* bnb = (const float*)d_in[5];
    const float* W2  = (const float*)d_in[6];
    const float* b2  = (const float*)d_in[7];
    const float* lng = (const float*)d_in[8];
    const float* lnb = (const float*)d_in[9];
    float* out = (float*)d_out;

    const int* src = ei;        // edge_index[0]
    const int* dst = ei + EE;   // edge_index[1]

    cudaFuncSetAttribute(nodeA_kernel, cudaFuncAttributeMaxDynamicSharedMemorySize, NODEA_SMEM);
    cudaFuncSetAttribute(nodeB_kernel, cudaFuncAttributeMaxDynamicSharedMemorySize, NODEB_SMEM);

    const int nscan = (NN + 1023) / 1024;   // 98

    hist_kernel<<<(EE + 255) / 256, 256>>>(dst);                               // 0
    scan1_kernel<<<nscan, 1024>>>();                                           // 1
    scan3_kernel<<<(NN + 255) / 256, 256>>>();                                 // 2
    scatter_kernel<<<(EE + 255) / 256, 256>>>(src, dst);                       // 3
    agg_kernel<<<(NN * 32 + 255) / 256, 256>>>((const float2*)x);              // 4
    nodeA_kernel<<<NBLKN, 256, NODEA_SMEM>>>(W1, b1);                          // 5
    bnfin_kernel<<<1, 1024>>>(bng, bnb);                                       // 6
    nodeB_kernel<<<NBLKN, 256, NODEB_SMEM>>>(W2, b2, lng, lnb, out);           // 7
}